// round 11
// baseline (speedup 1.0000x reference)
#include <cuda_runtime.h>
#include <math.h>

#define B_DIM 64
#define K_DIM 128
#define H_DIM 64
#define W_DIM 64
#define PLANE (H_DIM * W_DIM)          // 4096 floats = 1024 float4
#define N_PLANES (B_DIM * K_DIM)       // 8192
#define N_BOXES 256
#define ALPHA 1.0f
#define BETA 0.5f
#define NPART 32
#define PART_STRIDE 32                 // 128B between accumulator slots

#define THREADS 512
#define N_LOC_BLOCKS (N_BOXES / 2)     // 128 (2 boxes per block)
#define N_CLS_BLOCKS (N_PLANES / 2)    // 4096 (2 planes per block)
#define N_BLOCKS (N_LOC_BLOCKS + N_CLS_BLOCKS)   // 4224

// Zero-initialized device globals; finalize kernel resets them each run.
__device__ float g_cls_parts[NPART * PART_STRIDE];
__device__ float g_loc_parts[NPART * PART_STRIDE];

__device__ __forceinline__ float softplus_f(float x) {
    float ax = fabsf(x);
    return log1pf(expf(-ax)) + fmaxf(x, 0.0f);
}

// Monotonic float <-> uint encoding: float ordering == unsigned ordering.
__device__ __forceinline__ unsigned int enc_f(float f) {
    unsigned int u = __float_as_uint(f);
    return u ^ ((unsigned int)(((int)u) >> 31) | 0x80000000u);
}
__device__ __forceinline__ float dec_f(unsigned int e) {
    unsigned int u = (e & 0x80000000u) ? (e ^ 0x80000000u) : ~e;
    return __uint_as_float(u);
}

// 512 threads: two independent 256-thread halves, each owns one plane/box.
__global__ __launch_bounds__(THREADS, 4) void main_kernel(
    const float* __restrict__ cams,
    const float* __restrict__ concepts_gt,
    const int* __restrict__ box_b,
    const int* __restrict__ box_c,
    const int* __restrict__ y0v,
    const int* __restrict__ y1v,
    const int* __restrict__ x0v,
    const int* __restrict__ x1v)
{
    int t = threadIdx.x;
    int half = t >> 8;                 // 0 or 1
    int tt = t & 255;                  // index within half
    int wid = t >> 5;                  // 0..15 (warps 0-7 half0, 8-15 half1)
    int lid = t & 31;

    __shared__ float s0[16], s1[16];

    if (blockIdx.x < N_LOC_BLOCKS) {
        // ---------------- loc block: 2 boxes ----------------
        int box = blockIdx.x * 2 + half;
        int b = box_b[box];
        int c = box_c[box];
        int y0 = y0v[box], y1 = y1v[box], x0 = x0v[box], x1 = x1v[box];

        const float4* p = reinterpret_cast<const float4*>(
            cams + ((size_t)b * K_DIM + c) * PLANE);

        float inside = 0.0f, outside = 0.0f;
#pragma unroll
        for (int i = 0; i < 4; i++) {
            int u = i * 256 + tt;       // float4 index within plane [0,1024)
            float4 v = p[u];
            int row = u >> 4;           // 16 float4 per row (W=64)
            int col0 = (u & 15) << 2;
            float vals[4] = {v.x, v.y, v.z, v.w};
            bool rin = (row >= y0) && (row < y1);
#pragma unroll
            for (int j = 0; j < 4; j++) {
                int col = col0 + j;
                float e = __expf(-vals[j]);
                float s = __fdividef(1.0f, 1.0f + e);
                bool in = rin && (col >= x0) && (col < x1);
                float d = s - 1.0f;
                if (in) inside += d * d;
                else    outside += s * s;
            }
        }
#pragma unroll
        for (int off = 16; off > 0; off >>= 1) {
            inside  += __shfl_xor_sync(0xFFFFFFFFu, inside, off);
            outside += __shfl_xor_sync(0xFFFFFFFFu, outside, off);
        }
        if (lid == 0) { s0[wid] = inside; s1[wid] = outside; }
        __syncthreads();
        if (tt == 0) {                  // leaders of both halves run in parallel
            float ti = 0.0f, to = 0.0f;
            int base = half * 8;
#pragma unroll
            for (int w = 0; w < 8; w++) { ti += s0[base + w]; to += s1[base + w]; }
            float area = (float)((y1 - y0) * (x1 - x0));
            const float eps = 1e-6f;
            float loss = ti / (area + eps) + to / ((float)PLANE - area + eps);
            atomicAdd(&g_loc_parts[(box & (NPART - 1)) * PART_STRIDE], loss);
        }
    } else {
        // ---------------- cls block: 2 planes ----------------
        int plane = (blockIdx.x - N_LOC_BLOCKS) * 2 + half;
        const float4* p = reinterpret_cast<const float4*>(cams + (size_t)plane * PLANE);

        float m = -INFINITY;
#pragma unroll
        for (int i = 0; i < 4; i++) {
            float4 v = p[i * 256 + tt];
            m = fmaxf(m, fmaxf(fmaxf(v.x, v.y), fmaxf(v.z, v.w)));
        }
        // single-instruction warp max via REDUX on monotonic encoding
        unsigned int em = __reduce_max_sync(0xFFFFFFFFu, enc_f(m));
        if (lid == 0) s0[wid] = __uint_as_float(em);   // store encoded bits
        __syncthreads();
        if (tt == 0) {
            int base = half * 8;
            unsigned int e = __float_as_uint(s0[base]);
#pragma unroll
            for (int w = 1; w < 8; w++)
                e = max(e, __float_as_uint(s0[base + w]));
            float bm = dec_f(e);
            float y = concepts_gt[plane];
            float bce = y * softplus_f(-bm) + (1.0f - y) * softplus_f(bm);
            atomicAdd(&g_cls_parts[(plane & (NPART - 1)) * PART_STRIDE], bce);
        }
    }
}

// One warp: sum part slots, write out, reset slots.
// Kernel boundary orders kernel-1 atomics before these reads.
__global__ void finalize_kernel(float* __restrict__ out) {
    int lid = threadIdx.x;   // 32 threads
    float cls = g_cls_parts[lid * PART_STRIDE];
    float loc = g_loc_parts[lid * PART_STRIDE];
    g_cls_parts[lid * PART_STRIDE] = 0.0f;
    g_loc_parts[lid * PART_STRIDE] = 0.0f;
#pragma unroll
    for (int off = 16; off > 0; off >>= 1) {
        cls += __shfl_xor_sync(0xFFFFFFFFu, cls, off);
        loc += __shfl_xor_sync(0xFFFFFFFFu, loc, off);
    }
    if (lid == 0)
        out[0] = ALPHA * (cls / (float)N_PLANES) + BETA * (loc / (float)N_BOXES);
}

extern "C" void kernel_launch(void* const* d_in, const int* in_sizes, int n_in,
                              void* d_out, int out_size) {
    const float* cams        = (const float*)d_in[0];
    const float* concepts_gt = (const float*)d_in[1];
    const int*   box_b       = (const int*)d_in[2];
    const int*   box_c       = (const int*)d_in[3];
    const int*   y0          = (const int*)d_in[4];
    const int*   y1          = (const int*)d_in[5];
    const int*   x0          = (const int*)d_in[6];
    const int*   x1          = (const int*)d_in[7];
    float* out = (float*)d_out;

    main_kernel<<<N_BLOCKS, THREADS>>>(cams, concepts_gt, box_b, box_c, y0, y1, x0, x1);
    finalize_kernel<<<1, 32>>>(out);
}